// round 8
// baseline (speedup 1.0000x reference)
#include <cuda_runtime.h>
#include <cstdint>

#define BATCH 4
#define NPTS 4096
#define KOUT 16
#define NEED 31                 // rank 0 plus ranks 16..30
#define R2 256.0f
#define NTILES (NPTS / 32)      // 128
#define TPB 512
#define WARPS (TPB / 32)        // 16
#define NBLOCKS 296             // 148 SMs * 2 resident blocks
#define WPB_PER_BATCH ((NBLOCKS / BATCH) * WARPS)        // 1184
#define PERIOD (NPTS + WPB_PER_BATCH)                    // 5280
#define NK ((size_t)NPTS * KOUT)                         // 65536

// steal counters: never reset; q = ctr % PERIOD is deterministic per replay
__device__ unsigned g_ctr[BATCH];

// ---- packed f32x2 helpers (per-element .rn == scalar .rn, bit-exact) ----
__device__ __forceinline__ uint64_t lds64(uint32_t a) {
    uint64_t v;
    asm volatile("ld.shared.b64 %0, [%1];" : "=l"(v) : "r"(a));
    return v;
}
__device__ __forceinline__ uint64_t mul2(uint64_t a, uint64_t b) {
    uint64_t r;
    asm("mul.rn.f32x2 %0, %1, %2;" : "=l"(r) : "l"(a), "l"(b));
    return r;
}
__device__ __forceinline__ uint64_t add2(uint64_t a, uint64_t b) {
    uint64_t r;
    asm("add.rn.f32x2 %0, %1, %2;" : "=l"(r) : "l"(a), "l"(b));
    return r;
}
__device__ __forceinline__ uint64_t bcast2(float x) {
    uint64_t r;
    asm("mov.b64 %0, {%1, %1};" : "=l"(r) : "f"(x));
    return r;
}
__device__ __forceinline__ void unpack2(uint64_t v, float& lo, float& hi) {
    asm("mov.b64 {%0, %1}, %2;" : "=f"(lo), "=f"(hi) : "l"(v));
}
// packed d2 for 2 candidates: d2 = (qw + pw) + (-2)*dot, dot built in the
// reference's exact association order. Bit-identical to scalar version.
__device__ __forceinline__ uint64_t dist2p(
        uint64_t qx2, uint64_t qy2, uint64_t qz2, uint64_t qw2, uint64_t m2c,
        uint64_t px, uint64_t py, uint64_t pz, uint64_t pw) {
    uint64_t dot = add2(add2(mul2(qx2, px), mul2(qy2, py)), mul2(qz2, pz));
    return add2(add2(qw2, pw), mul2(m2c, dot));
}

// smem pair-SoA: chunk j (tiles 2j, 2j+1), 256 floats:
//   X[64] @ +0, Y[64] @ +64, Z[64] @ +128, W[64] @ +192 (float indices)
//   element i -> chunk i>>6, slot (i&31)*2 + ((i>>5)&1)
__device__ __forceinline__ int sidx(int i) {
    return ((i >> 6) << 8) + ((i & 31) << 1) + ((i >> 5) & 1);
}

// ---------------------------------------------------------------------------
// Fused kernel: ball query (packed f32x2 scan) + dilated selection +
// transposing gather epilogue. Warp per query, work-stealing.
// ---------------------------------------------------------------------------
__global__ void __launch_bounds__(TPB, 2) fused_kernel(
        const float* __restrict__ xyz,
        const float* __restrict__ feat,
        float* __restrict__ out) {
    extern __shared__ float sm[];                       // 64KB pair-SoA
    __shared__ __align__(16) unsigned words[WARPS][NTILES];
    __shared__ int oid[WARPS][KOUT + 1];
    __shared__ float4 stage[WARPS][128];                // 16 rows x 8 f4 = 2KB

    int b = blockIdx.x % BATCH;
    const float* xb = xyz + (size_t)b * NPTS * 3;

    for (int i = threadIdx.x; i < NPTS; i += blockDim.x) {
        float x = xb[3 * i + 0];
        float y = xb[3 * i + 1];
        float z = xb[3 * i + 2];
        float nq = __fadd_rn(__fadd_rn(__fmul_rn(x, x), __fmul_rn(y, y)),
                             __fmul_rn(z, z));
        int fi = sidx(i);
        sm[fi]       = x;
        sm[fi + 64]  = y;
        sm[fi + 128] = z;
        sm[fi + 192] = nq;
    }
    __syncthreads();

    uint32_t sbase;
    asm("{ .reg .u64 t; cvta.to.shared.u64 t, %1; cvt.u32.u64 %0, t; }"
        : "=r"(sbase) : "l"(sm));

    int warp = threadIdx.x >> 5;
    int lane = threadIdx.x & 31;
    const float* fb = feat + (size_t)b * NPTS * 64;
    float* outx = out + ((size_t)b * 3) * NK;                 // xyz block
    float* outf = out + (size_t)BATCH * 3 * NK + ((size_t)b * 64) * NK;
    const uint64_t m2c = bcast2(-2.0f);

    for (;;) {
        unsigned qr = 0;
        if (lane == 0) qr = atomicAdd(&g_ctr[b], 1u) % PERIOD;
        int q = __shfl_sync(0xffffffffu, (int)qr, 0);
        if (q >= NPTS) break;

        // query point (broadcast LDS; all lanes same address)
        int qi = sidx(q);
        uint64_t qx2 = bcast2(sm[qi]);
        uint64_t qy2 = bcast2(sm[qi + 64]);
        uint64_t qz2 = bcast2(sm[qi + 128]);
        uint64_t qw2 = bcast2(sm[qi + 192]);

        int cnt = 0;
        int tscan = NTILES;

        // ---- scan: 2 chunks (4 tiles, 128 candidates) per iteration ----
        {
            uint32_t sp = sbase + lane * 8;
            for (int c = 0; c < NTILES; c += 4, sp += 2048) {
                uint64_t ax = lds64(sp);
                uint64_t ay = lds64(sp + 256);
                uint64_t az = lds64(sp + 512);
                uint64_t aw = lds64(sp + 768);
                uint64_t bx = lds64(sp + 1024);
                uint64_t by = lds64(sp + 1280);
                uint64_t bz = lds64(sp + 1536);
                uint64_t bw = lds64(sp + 1792);
                uint64_t dA = dist2p(qx2, qy2, qz2, qw2, m2c, ax, ay, az, aw);
                uint64_t dB = dist2p(qx2, qy2, qz2, qw2, m2c, bx, by, bz, bw);
                float d0, d1, d2, d3;
                unpack2(dA, d0, d1);     // tiles c, c+1
                unpack2(dB, d2, d3);     // tiles c+2, c+3
                unsigned m0 = __ballot_sync(0xffffffffu, d0 < R2);
                unsigned m1 = __ballot_sync(0xffffffffu, d1 < R2);
                unsigned m2 = __ballot_sync(0xffffffffu, d2 < R2);
                unsigned m3 = __ballot_sync(0xffffffffu, d3 < R2);
                if (lane == 0)
                    *(uint4*)&words[warp][c] = make_uint4(m0, m1, m2, m3);
                cnt += __popc(m0) + __popc(m1) + __popc(m2) + __popc(m3);
                if (cnt >= NEED) { tscan = c + 4; break; }
            }
        }
        __syncwarp();

        // ---- decode: rank 0 and ranks 16..30 from mask words ----
        int base = 0;
#pragma unroll
        for (int g = 0; g < 4; g++) {
            if (base >= NEED) break;
            int wi = 32 * g + lane;
            unsigned w = (wi < tscan) ? words[warp][wi] : 0u;
            int pc = __popc(w);
            int pre = pc;                          // inclusive warp scan
#pragma unroll
            for (int o = 1; o < 32; o <<= 1) {
                int t = __shfl_up_sync(0xffffffffu, pre, o);
                if (lane >= o) pre += t;
            }
            int lo = base + pre - pc;              // first rank in my word
            if (w && lo < NEED) {
                unsigned ww = w;
                int r = lo;
                while (ww && r < NEED) {
                    int bit = __ffs(ww) - 1;
                    ww &= ww - 1;
                    if (r == 0)
                        oid[warp][0] = 32 * wi + bit;
                    else if (r >= 16)
                        oid[warp][r - 15] = 32 * wi + bit;
                    r++;
                }
            }
            base += __shfl_sync(0xffffffffu, pre, 31);
        }
        __syncwarp();

        // finalize ids (padding with first hit) back into oid[warp][k]
        if (lane < KOUT) {
            int v = (lane > 0 && cnt >= lane + 16) ? oid[warp][lane]
                                                   : oid[warp][0];
            oid[warp][lane] = v;
        }
        __syncwarp();

        // ---- gather epilogue ----
        // xyz: from pair-SoA smem (lanes 0..15, k = lane)
        if (lane < KOUT) {
            int id = oid[warp][lane];
            int fi = sidx(id);
            size_t ox = (size_t)q * KOUT + lane;
            outx[ox]          = sm[fi];
            outx[ox + NK]     = sm[fi + 64];
            outx[ox + 2 * NK] = sm[fi + 128];
        }

        // feat: 2 passes over channel halves; coalesced row loads ->
        // XOR-swizzled stage -> channel-major 64B-segment stores.
        int ldrow = lane >> 3;           // 0..3 row-within-group
        int ldlc  = lane & 7;            // chunk within half
        int k     = lane & 15;
        int sub   = lane >> 4;
#pragma unroll
        for (int p = 0; p < 2; p++) {
#pragma unroll
            for (int i = 0; i < 4; i++) {
                int row = 4 * i + ldrow;
                int id = oid[warp][row];
                float4 v = *((const float4*)(fb + (size_t)id * 64)
                             + (p * 8 + ldlc));
                stage[warp][row * 8 + (ldlc ^ (row & 7))] = v;
            }
            __syncwarp();
#pragma unroll
            for (int t = 0; t < 4; t++) {
                int lc = sub * 4 + t;
                float4 v = stage[warp][k * 8 + (lc ^ (k & 7))];
                float* o = outf + (size_t)((p * 8 + lc) * 4) * NK
                                + (size_t)q * KOUT + k;
                o[0]      = v.x;
                o[NK]     = v.y;
                o[2 * NK] = v.z;
                o[3 * NK] = v.w;
            }
            __syncwarp();
        }
    }
}

extern "C" void kernel_launch(void* const* d_in, const int* in_sizes, int n_in,
                              void* d_out, int out_size) {
    const float* xyz  = (const float*)d_in[0];
    const float* feat = (const float*)d_in[1];
    float* out = (float*)d_out;

    cudaFuncSetAttribute(fused_kernel,
                         cudaFuncAttributeMaxDynamicSharedMemorySize,
                         NPTS * 4 * sizeof(float));

    fused_kernel<<<NBLOCKS, TPB, NPTS * 4 * sizeof(float)>>>(xyz, feat, out);
}